// round 15
// baseline (speedup 1.0000x reference)
#include <cuda_runtime.h>
#include <cuda_bf16.h>
#include <cuda_fp16.h>
#include <cuda_fp8.h>
#include <math.h>
#include <stdint.h>

#define B 2
#define D 128
#define P 3600
#define NN 57600
#define C 19
#define GAMMA 0.75f
#define EPS 1e-8f

#define PTILES 29        // ceil(3600/128)
#define NTILES 450       // 57600/128
#define SPLIT 15
#define TPC 30           // n-tiles per CTA = 450/15

// dynamic smem: A(16K) + 2x B(16K) + 2x NL(256B)
#define OFF_A    0
#define OFF_B0   16384
#define OFF_B1   32768
#define OFF_NL0  49152
#define OFF_NL1  49408
#define SMEM_BYTES 49664

#define LOG2E10 14.4269504089f   // 10 * log2(e)

// -------- device global scratch (no allocation allowed) --------
// A fragments (e4m3, pre-scaled by 10*log2e): [b][pt][ks 4][mf 8][lane 32][4 u32]
static __device__ __align__(16) uint32_t g_afr[B * PTILES * 4096];
// B fragments (e4m3): [b][nt][wn 4][ks 4][nqL 2][lane 32][4 u32]
static __device__ __align__(16) uint32_t g_bfr[B * NTILES * 4096];
static __device__ __align__(16) uint16_t g_nlh[B * NN];   // neg labels as f16 bits
static __device__ int   g_labels1[B * P];
static __device__ float g_mask1[B * P];
static __device__ float g_pos1[B * P];
static __device__ float g_negsum[B * P];

// -------- PTX helpers --------
__device__ __forceinline__ uint32_t smem_u32(const void* p) {
    uint32_t a;
    asm("{ .reg .u64 t; cvta.to.shared.u64 t, %1; cvt.u32.u64 %0, t; }" : "=r"(a) : "l"(p));
    return a;
}
__device__ __forceinline__ void cp16(uint32_t dst, const void* src) {
    asm volatile("cp.async.cg.shared.global [%0], [%1], 16;" :: "r"(dst), "l"(src));
}

// -------- zero accumulators --------
__global__ void k_zero() {
    int i = blockIdx.x * blockDim.x + threadIdx.x;
    if (i < B * P) g_negsum[i] = 0.0f;
}

// -------- neg labels: argmax over C, stored as f16 --------
__global__ void k_neglabels(const float* __restrict__ npl) {
    int i = blockIdx.x * blockDim.x + threadIdx.x;
    if (i >= B * NN) return;
    int b = i / NN, n = i % NN;
    const float* base = npl + (size_t)b * C * NN + n;
    float best = base[0];
    int bi = 0;
#pragma unroll
    for (int c = 1; c < C; ++c) {
        float v = base[(size_t)c * NN];
        if (v > best) { best = v; bi = c; }
    }
    __half h = __int2half_rn(bi);
    g_nlh[i] = __half_as_ushort(h);
}

// -------- anchor precompute: pos1 (fp32), labels1, mask1 --------
__global__ void k_anchor(const float* __restrict__ f1, const float* __restrict__ f2,
                         const float* __restrict__ pl1, const float* __restrict__ pl2) {
    int i = blockIdx.x * blockDim.x + threadIdx.x;
    if (i >= B * P) return;
    int b = i / P, p = i % P;

    const float* a  = f1 + (size_t)b * D * P + p;
    const float* bb = f2 + (size_t)b * D * P + p;
    float s = 0.0f;
#pragma unroll 16
    for (int d = 0; d < D; ++d) s += a[(size_t)d * P] * bb[(size_t)d * P];
    g_pos1[i] = s * 10.0f;

    const float* q1 = pl1 + (size_t)b * C * P + p;
    const float* q2 = pl2 + (size_t)b * C * P + p;
    float best = q1[0];
    int bi = 0, m = 0;
    bool found = ((q1[0] < q2[0]) && (q2[0] > GAMMA));
#pragma unroll
    for (int c = 1; c < C; ++c) {
        float v1 = q1[(size_t)c * P], v2 = q2[(size_t)c * P];
        if (v1 > best) { best = v1; bi = c; }
        if (!found && (v1 < v2) && (v2 > GAMMA)) { found = true; m = c; }
    }
    g_labels1[i] = bi;
    g_mask1[i]   = (float)m;
}

// -------- pack helper: 4 floats -> 4 e4m3 bytes in a u32 --------
__device__ __forceinline__ uint32_t pack_fp8x4(float v0, float v1, float v2, float v3) {
    uint32_t b0 = __nv_cvt_float_to_fp8(v0, __NV_SATFINITE, __NV_E4M3);
    uint32_t b1 = __nv_cvt_float_to_fp8(v1, __NV_SATFINITE, __NV_E4M3);
    uint32_t b2 = __nv_cvt_float_to_fp8(v2, __NV_SATFINITE, __NV_E4M3);
    uint32_t b3 = __nv_cvt_float_to_fp8(v3, __NV_SATFINITE, __NV_E4M3);
    return b0 | (b1 << 8) | (b2 << 16) | (b3 << 24);
}

// -------- convert neg feats -> e4m3 B fragments, warp_n-sliced layout --------
// src mapping bits: q[0:1] lane[2:6] nq[7:9] ks[10:11]; nf = nq*2+(q>>1), r = q&1
// dst u32 index: wn*1024 + ks*256 + nqL*128 + lane*4 + q  (wn = nq>>1, nqL = nq&1)
__global__ void k_convert_neg(const float* __restrict__ neg) {
    int nt = blockIdx.x, b = blockIdx.y;
    const float* src = neg + (size_t)b * D * NN;
    uint32_t* dst = g_bfr + (size_t)(b * NTILES + nt) * 4096;
#pragma unroll
    for (int it = 0; it < 16; ++it) {
        int o = threadIdx.x + it * 256;
        int q    = o & 3;
        int lane = (o >> 2) & 31;
        int nq   = (o >> 7) & 7;
        int ks   = o >> 10;
        int nf = nq * 2 + (q >> 1);
        int r  = q & 1;
        int n  = nt * 128 + nf * 8 + (lane >> 2);
        int kb = ks * 32 + (lane & 3) * 4 + r * 16;
        float v0 = src[(size_t)(kb + 0) * NN + n];
        float v1 = src[(size_t)(kb + 1) * NN + n];
        float v2 = src[(size_t)(kb + 2) * NN + n];
        float v3 = src[(size_t)(kb + 3) * NN + n];
        int wn = nq >> 1, nqL = nq & 1;
        dst[wn * 1024 + ks * 256 + nqL * 128 + lane * 4 + q] = pack_fp8x4(v0, v1, v2, v3);
    }
}

// -------- convert anchor feats -> e4m3 A fragments, PRE-SCALED by 10*log2e --------
// u32 layout bits: r[0:1] lane[2:6] mf[7:9] ks[10:11]
__global__ void k_convert_a(const float* __restrict__ f1) {
    int pt = blockIdx.x, b = blockIdx.y;
    const float* src = f1 + (size_t)b * D * P;
    uint32_t* dst = g_afr + (size_t)(b * PTILES + pt) * 4096;
#pragma unroll
    for (int it = 0; it < 16; ++it) {
        int o = threadIdx.x + it * 256;
        int r    = o & 3;
        int lane = (o >> 2) & 31;
        int mf   = (o >> 7) & 7;
        int ks   = o >> 10;
        int row = mf * 16 + (lane >> 2) + (r & 1) * 8;
        int kb  = ks * 32 + (lane & 3) * 4 + (r >> 1) * 16;
        int p   = pt * 128 + row;
        float v0 = 0.f, v1 = 0.f, v2 = 0.f, v3 = 0.f;
        if (p < P) {
            v0 = src[(size_t)(kb + 0) * P + p] * LOG2E10;
            v1 = src[(size_t)(kb + 1) * P + p] * LOG2E10;
            v2 = src[(size_t)(kb + 2) * P + p] * LOG2E10;
            v3 = src[(size_t)(kb + 3) * P + p] * LOG2E10;
        }
        dst[o] = pack_fp8x4(v0, v1, v2, v3);
    }
}

// -------- fp8 mma.sync wrapper --------
__device__ __forceinline__ void qmma(float* c, const uint32_t* a, const uint32_t* bb) {
    asm volatile(
        "mma.sync.aligned.m16n8k32.row.col.f32.e4m3.e4m3.f32 "
        "{%0,%1,%2,%3}, {%4,%5,%6,%7}, {%8,%9}, {%0,%1,%2,%3};"
        : "+f"(c[0]), "+f"(c[1]), "+f"(c[2]), "+f"(c[3])
        : "r"(a[0]), "r"(a[1]), "r"(a[2]), "r"(a[3]), "r"(bb[0]), "r"(bb[1]));
}

// -------- main: 128x128 tiles, mf-outer passes (16 live accumulators), 3 CTAs/SM --------
extern __shared__ char smem_dyn[];

__global__ void __launch_bounds__(256, 3) k_main() {
    char* smem = smem_dyn;
    const uint32_t sbase = smem_u32(smem);
    const int tid  = threadIdx.x;
    const int wid  = tid >> 5;
    const int lane = tid & 31;
    const int pt = blockIdx.x, sp = blockIdx.y, b = blockIdx.z;
    const int warp_m = wid >> 2;   // 0..1 -> 64 rows
    const int warp_n = wid & 3;    // 0..3 -> 32 cols

    const uint32_t* afr  = g_afr + (size_t)(b * PTILES + pt) * 4096;
    const int tile0 = sp * TPC;
    const uint32_t* bfr0 = g_bfr + (size_t)(b * NTILES + tile0) * 4096;
    const uint16_t* nl0 = g_nlh + b * NN + tile0 * 128;

    // prologue group 0: A tile + B tile 0 + labels 0
#pragma unroll
    for (int i = 0; i < 4; ++i)
        cp16(sbase + OFF_A + ((tid + (i << 8)) << 4), afr + ((tid + (i << 8)) << 2));
#pragma unroll
    for (int i = 0; i < 4; ++i)
        cp16(sbase + OFF_B0 + ((tid + (i << 8)) << 4), bfr0 + ((tid + (i << 8)) << 2));
    if (tid < 16) cp16(sbase + OFF_NL0 + (tid << 4), nl0 + (tid << 3));
    asm volatile("cp.async.commit_group;");

    // row labels as replicated f16x2
    uint32_t rl2[4][2];
#pragma unroll
    for (int mf = 0; mf < 4; ++mf)
#pragma unroll
        for (int h = 0; h < 2; ++h) {
            int p = pt * 128 + warp_m * 64 + mf * 16 + (lane >> 2) + h * 8;
            float frl = (p < P) ? (float)g_labels1[b * P + p] : -1.0f;
            asm("cvt.rn.f16x2.f32 %0, %1, %1;" : "=r"(rl2[mf][h]) : "f"(frl));
        }

    float racc[4][2];
    uint32_t tacc[4][2];
#pragma unroll
    for (int mf = 0; mf < 4; ++mf)
#pragma unroll
        for (int h = 0; h < 2; ++h) { racc[mf][h] = 0.f; tacc[mf][h] = 0u; }

    for (int t = 0; t < TPC; ++t) {
        const int buf = t & 1;
        // prefetch tile t+1 into the other buffer
        if (t + 1 < TPC) {
            const int nb = buf ^ 1;
            const uint32_t* bs = bfr0 + (size_t)(t + 1) * 4096;
            const uint32_t bd = sbase + (nb ? OFF_B1 : OFF_B0);
#pragma unroll
            for (int i = 0; i < 4; ++i)
                cp16(bd + ((tid + (i << 8)) << 4), bs + ((tid + (i << 8)) << 2));
            if (tid < 16)
                cp16(sbase + (nb ? OFF_NL1 : OFF_NL0) + (tid << 4),
                     nl0 + (t + 1) * 128 + (tid << 3));
        }
        asm volatile("cp.async.commit_group;");
        asm volatile("cp.async.wait_group 1;");   // tile t's group complete
        __syncthreads();

        const char* sbB = smem + (buf ? OFF_B1 : OFF_B0) + warp_n * 4096;
        const uint32_t* nlS = (const uint32_t*)(smem + (buf ? OFF_NL1 : OFF_NL0))
                              + warp_n * 16 + (lane & 3);
        uint32_t cl2[4] = { nlS[0], nlS[4], nlS[8], nlS[12] };

        // four mf-passes: 16 live accumulators each, epilogue fused per pass
#pragma unroll
        for (int mf = 0; mf < 4; ++mf) {
            float c[4][4];
#pragma unroll
            for (int nf = 0; nf < 4; ++nf)
#pragma unroll
                for (int k = 0; k < 4; ++k) c[nf][k] = 0.f;

#pragma unroll
            for (int ks = 0; ks < 4; ++ks) {
                const uint4 b0 = *(const uint4*)(sbB + ((ks * 256 + lane * 4) << 2));
                const uint4 b1 = *(const uint4*)(sbB + ((ks * 256 + 128 + lane * 4) << 2));
                uint32_t br0[2] = {b0.x, b0.y};
                uint32_t br1[2] = {b0.z, b0.w};
                uint32_t br2[2] = {b1.x, b1.y};
                uint32_t br3[2] = {b1.z, b1.w};
                const uint4 av = *(const uint4*)
                    (smem + OFF_A + (((ks * 8 + warp_m * 4 + mf) * 32 + lane) << 4));
                uint32_t ar[4] = {av.x, av.y, av.z, av.w};
                qmma(c[0], ar, br0);
                qmma(c[1], ar, br1);
                qmma(c[2], ar, br2);
                qmma(c[3], ar, br3);
            }

            // epilogue for this mf, fully packed f16x2
#pragma unroll
            for (int nf = 0; nf < 4; ++nf) {
#pragma unroll
                for (int h = 0; h < 2; ++h) {
                    uint32_t t01, msk;
                    asm("cvt.rn.f16x2.f32 %0, %1, %2;"
                        : "=r"(t01)
                        : "f"(c[nf][h * 2 + 1]), "f"(c[nf][h * 2 + 0]));
                    asm("ex2.approx.f16x2 %0, %1;" : "=r"(t01) : "r"(t01));
                    asm("set.ne.f16x2.f16x2 %0, %1, %2;"
                        : "=r"(msk) : "r"(rl2[mf][h]), "r"(cl2[nf]));
                    asm("fma.rn.f16x2 %0, %1, %2, %0;"
                        : "+r"(tacc[mf][h]) : "r"(t01), "r"(msk));
                }
            }
        }

        // drain packed accumulators to f32 every 2nd tile
        if (t & 1) {
#pragma unroll
            for (int mf = 0; mf < 4; ++mf)
#pragma unroll
                for (int h = 0; h < 2; ++h) {
                    float lo, hi;
                    asm("{ .reg .b16 l, u;\n\t"
                        "  mov.b32 {l, u}, %2;\n\t"
                        "  cvt.f32.f16 %0, l;\n\t"
                        "  cvt.f32.f16 %1, u; }"
                        : "=f"(lo), "=f"(hi) : "r"(tacc[mf][h]));
                    racc[mf][h] += lo + hi;
                    tacc[mf][h] = 0u;
                }
        }
        __syncthreads();   // all warps done with buf before it is overwritten
    }

    // final drain (TPC=30 even, tacc already drained; keep safe)
#pragma unroll
    for (int mf = 0; mf < 4; ++mf)
#pragma unroll
        for (int h = 0; h < 2; ++h) {
            float lo, hi;
            asm("{ .reg .b16 l, u;\n\t"
                "  mov.b32 {l, u}, %2;\n\t"
                "  cvt.f32.f16 %0, l;\n\t"
                "  cvt.f32.f16 %1, u; }"
                : "=f"(lo), "=f"(hi) : "r"(tacc[mf][h]));
            racc[mf][h] += lo + hi;
        }

    // reduce across the 4 lanes of each quad (they share rows), then atomadd
#pragma unroll
    for (int mf = 0; mf < 4; ++mf)
#pragma unroll
        for (int h = 0; h < 2; ++h) {
            float v = racc[mf][h];
            v += __shfl_xor_sync(0xffffffffu, v, 1);
            v += __shfl_xor_sync(0xffffffffu, v, 2);
            if ((lane & 3) == 0) {
                int p = pt * 128 + warp_m * 64 + mf * 16 + (lane >> 2) + h * 8;
                if (p < P) atomicAdd(&g_negsum[b * P + p], v);
            }
        }
}

// -------- finalize --------
__global__ void k_final(float* __restrict__ out) {
    const int tid = threadIdx.x;
    float sl[2] = {0.f, 0.f}, sm[2] = {0.f, 0.f};
    for (int p = tid; p < P; p += blockDim.x) {
#pragma unroll
        for (int b = 0; b < 2; ++b) {
            int i = b * P + p;
            float pe    = expf(g_pos1[i]);
            float ns    = g_negsum[i];
            float lossn = -logf(pe / (pe + ns + EPS) + EPS);
            float m     = g_mask1[i];
            sl[b] += m * lossn;
            sm[b] += m;
        }
    }
    __shared__ float red[4][256];
    red[0][tid] = sl[0]; red[1][tid] = sl[1];
    red[2][tid] = sm[0]; red[3][tid] = sm[1];
    __syncthreads();
    for (int s = 128; s > 0; s >>= 1) {
        if (tid < s) {
#pragma unroll
            for (int k = 0; k < 4; ++k) red[k][tid] += red[k][tid + s];
        }
        __syncthreads();
    }
    if (tid == 0) {
        float l0 = red[0][0] / (red[2][0] + EPS);
        float l1 = red[1][0] / (red[3][0] + EPS);
        out[0] = 0.1f * (l0 + l1);
    }
}

// -------- launch --------
extern "C" void kernel_launch(void* const* d_in, const int* in_sizes, int n_in,
                              void* d_out, int out_size) {
    const float* feats_view1 = (const float*)d_in[0];  // [B,D,240,240]
    const float* pos_feats1  = (const float*)d_in[1];  // [B,D,60,60]
    const float* pos_feats2  = (const float*)d_in[2];  // [B,D,60,60]
    const float* pl1         = (const float*)d_in[3];
    const float* pl2         = (const float*)d_in[4];
    const float* npl         = (const float*)d_in[5];  // [B,C,240,240]

    cudaFuncSetAttribute(k_main, cudaFuncAttributeMaxDynamicSharedMemorySize, SMEM_BYTES);

    k_zero<<<(B * P + 255) / 256, 256>>>();
    k_neglabels<<<(B * NN + 255) / 256, 256>>>(npl);
    k_anchor<<<(B * P + 127) / 128, 128>>>(pos_feats1, pos_feats2, pl1, pl2);
    k_convert_neg<<<dim3(NTILES, B), 256>>>(feats_view1);
    k_convert_a<<<dim3(PTILES, B), 256>>>(pos_feats1);

    k_main<<<dim3(PTILES, SPLIT, B), 256, SMEM_BYTES>>>();

    k_final<<<1, 256>>>((float*)d_out);
}

// round 16
// speedup vs baseline: 1.5828x; 1.5828x over previous
#include <cuda_runtime.h>
#include <cuda_bf16.h>
#include <cuda_fp16.h>
#include <cuda_fp8.h>
#include <math.h>
#include <stdint.h>

#define B 2
#define D 128
#define P 3600
#define NN 57600
#define C 19
#define GAMMA 0.75f
#define EPS 1e-8f

#define PTILES 29        // ceil(3600/128)
#define NTILES 450       // 57600/128
#define SPLIT 5
#define TPC 90           // n-tiles per CTA

// dynamic smem: A(16K) + 8 warps x 2 bufs x 4KB B slices + labels
#define OFF_A    0        // 16384
#define OFF_B    16384    // + (wid*2+buf)*4096, 65536 total
#define OFF_NL   81920    // + (wid*2+buf)*64, 1024 total
#define SMEM_BYTES 82944

#define LOG2E10 14.4269504089f   // 10 * log2(e)

// -------- device global scratch (no allocation allowed) --------
// A fragments (e4m3, pre-scaled by 10*log2e): [b][pt][ks 4][mf 8][lane 32][4 u32]
static __device__ __align__(16) uint32_t g_afr[B * PTILES * 4096];
// B fragments (e4m3): [b][nt][wn 4][ks 4][nqL 2][lane 32][4 u32]
static __device__ __align__(16) uint32_t g_bfr[B * NTILES * 4096];
static __device__ __align__(16) uint16_t g_nlh[B * NN];   // neg labels as f16 bits
static __device__ int   g_labels1[B * P];
static __device__ float g_mask1[B * P];
static __device__ float g_pos1[B * P];
static __device__ float g_negsum[B * P];

// -------- PTX helpers --------
__device__ __forceinline__ uint32_t smem_u32(const void* p) {
    uint32_t a;
    asm("{ .reg .u64 t; cvta.to.shared.u64 t, %1; cvt.u32.u64 %0, t; }" : "=r"(a) : "l"(p));
    return a;
}
__device__ __forceinline__ void cp16(uint32_t dst, const void* src) {
    asm volatile("cp.async.cg.shared.global [%0], [%1], 16;" :: "r"(dst), "l"(src));
}

// -------- zero accumulators --------
__global__ void k_zero() {
    int i = blockIdx.x * blockDim.x + threadIdx.x;
    if (i < B * P) g_negsum[i] = 0.0f;
}

// -------- neg labels: argmax over C, stored as f16 --------
__global__ void k_neglabels(const float* __restrict__ npl) {
    int i = blockIdx.x * blockDim.x + threadIdx.x;
    if (i >= B * NN) return;
    int b = i / NN, n = i % NN;
    const float* base = npl + (size_t)b * C * NN + n;
    float best = base[0];
    int bi = 0;
#pragma unroll
    for (int c = 1; c < C; ++c) {
        float v = base[(size_t)c * NN];
        if (v > best) { best = v; bi = c; }
    }
    __half h = __int2half_rn(bi);
    g_nlh[i] = __half_as_ushort(h);
}

// -------- anchor precompute: pos1 (fp32), labels1, mask1 --------
__global__ void k_anchor(const float* __restrict__ f1, const float* __restrict__ f2,
                         const float* __restrict__ pl1, const float* __restrict__ pl2) {
    int i = blockIdx.x * blockDim.x + threadIdx.x;
    if (i >= B * P) return;
    int b = i / P, p = i % P;

    const float* a  = f1 + (size_t)b * D * P + p;
    const float* bb = f2 + (size_t)b * D * P + p;
    float s = 0.0f;
#pragma unroll 16
    for (int d = 0; d < D; ++d) s += a[(size_t)d * P] * bb[(size_t)d * P];
    g_pos1[i] = s * 10.0f;

    const float* q1 = pl1 + (size_t)b * C * P + p;
    const float* q2 = pl2 + (size_t)b * C * P + p;
    float best = q1[0];
    int bi = 0, m = 0;
    bool found = ((q1[0] < q2[0]) && (q2[0] > GAMMA));
#pragma unroll
    for (int c = 1; c < C; ++c) {
        float v1 = q1[(size_t)c * P], v2 = q2[(size_t)c * P];
        if (v1 > best) { best = v1; bi = c; }
        if (!found && (v1 < v2) && (v2 > GAMMA)) { found = true; m = c; }
    }
    g_labels1[i] = bi;
    g_mask1[i]   = (float)m;
}

// -------- pack helper: 4 floats -> 4 e4m3 bytes in a u32 --------
__device__ __forceinline__ uint32_t pack_fp8x4(float v0, float v1, float v2, float v3) {
    uint32_t b0 = __nv_cvt_float_to_fp8(v0, __NV_SATFINITE, __NV_E4M3);
    uint32_t b1 = __nv_cvt_float_to_fp8(v1, __NV_SATFINITE, __NV_E4M3);
    uint32_t b2 = __nv_cvt_float_to_fp8(v2, __NV_SATFINITE, __NV_E4M3);
    uint32_t b3 = __nv_cvt_float_to_fp8(v3, __NV_SATFINITE, __NV_E4M3);
    return b0 | (b1 << 8) | (b2 << 16) | (b3 << 24);
}

// -------- convert neg feats -> e4m3 B fragments, warp_n-sliced layout --------
// src mapping bits: q[0:1] lane[2:6] nq[7:9] ks[10:11]; nf = nq*2+(q>>1), r = q&1
// dst u32 index: wn*1024 + ks*256 + nqL*128 + lane*4 + q  (wn = nq>>1, nqL = nq&1)
__global__ void k_convert_neg(const float* __restrict__ neg) {
    int nt = blockIdx.x, b = blockIdx.y;
    const float* src = neg + (size_t)b * D * NN;
    uint32_t* dst = g_bfr + (size_t)(b * NTILES + nt) * 4096;
#pragma unroll
    for (int it = 0; it < 16; ++it) {
        int o = threadIdx.x + it * 256;
        int q    = o & 3;
        int lane = (o >> 2) & 31;
        int nq   = (o >> 7) & 7;
        int ks   = o >> 10;
        int nf = nq * 2 + (q >> 1);
        int r  = q & 1;
        int n  = nt * 128 + nf * 8 + (lane >> 2);
        int kb = ks * 32 + (lane & 3) * 4 + r * 16;
        float v0 = src[(size_t)(kb + 0) * NN + n];
        float v1 = src[(size_t)(kb + 1) * NN + n];
        float v2 = src[(size_t)(kb + 2) * NN + n];
        float v3 = src[(size_t)(kb + 3) * NN + n];
        int wn = nq >> 1, nqL = nq & 1;
        dst[wn * 1024 + ks * 256 + nqL * 128 + lane * 4 + q] = pack_fp8x4(v0, v1, v2, v3);
    }
}

// -------- convert anchor feats -> e4m3 A fragments, PRE-SCALED by 10*log2e --------
// u32 layout bits: r[0:1] lane[2:6] mf[7:9] ks[10:11]
__global__ void k_convert_a(const float* __restrict__ f1) {
    int pt = blockIdx.x, b = blockIdx.y;
    const float* src = f1 + (size_t)b * D * P;
    uint32_t* dst = g_afr + (size_t)(b * PTILES + pt) * 4096;
#pragma unroll
    for (int it = 0; it < 16; ++it) {
        int o = threadIdx.x + it * 256;
        int r    = o & 3;
        int lane = (o >> 2) & 31;
        int mf   = (o >> 7) & 7;
        int ks   = o >> 10;
        int row = mf * 16 + (lane >> 2) + (r & 1) * 8;
        int kb  = ks * 32 + (lane & 3) * 4 + (r >> 1) * 16;
        int p   = pt * 128 + row;
        float v0 = 0.f, v1 = 0.f, v2 = 0.f, v3 = 0.f;
        if (p < P) {
            v0 = src[(size_t)(kb + 0) * P + p] * LOG2E10;
            v1 = src[(size_t)(kb + 1) * P + p] * LOG2E10;
            v2 = src[(size_t)(kb + 2) * P + p] * LOG2E10;
            v3 = src[(size_t)(kb + 3) * P + p] * LOG2E10;
        }
        dst[o] = pack_fp8x4(v0, v1, v2, v3);
    }
}

// -------- fp8 mma.sync wrapper --------
__device__ __forceinline__ void qmma(float* c, const uint32_t* a, const uint32_t* bb) {
    asm volatile(
        "mma.sync.aligned.m16n8k32.row.col.f32.e4m3.e4m3.f32 "
        "{%0,%1,%2,%3}, {%4,%5,%6,%7}, {%8,%9}, {%0,%1,%2,%3};"
        : "+f"(c[0]), "+f"(c[1]), "+f"(c[2]), "+f"(c[3])
        : "r"(a[0]), "r"(a[1]), "r"(a[2]), "r"(a[3]), "r"(bb[0]), "r"(bb[1]));
}

// epilogue for one mf-group of accumulators (packed f16x2 path)
#define EPILOGUE_MF(cc, mf_)                                                     \
    do {                                                                         \
        _Pragma("unroll")                                                        \
        for (int nf = 0; nf < 4; ++nf) {                                         \
            _Pragma("unroll")                                                    \
            for (int h = 0; h < 2; ++h) {                                        \
                uint32_t t01, msk;                                               \
                asm("cvt.rn.f16x2.f32 %0, %1, %2;"                               \
                    : "=r"(t01)                                                  \
                    : "f"((cc)[nf][h * 2 + 1]), "f"((cc)[nf][h * 2 + 0]));       \
                asm("ex2.approx.f16x2 %0, %1;" : "=r"(t01) : "r"(t01));          \
                asm("set.ne.f16x2.f16x2 %0, %1, %2;"                             \
                    : "=r"(msk) : "r"(rl2[mf_][h]), "r"(cl2[nf]));               \
                asm("fma.rn.f16x2 %0, %1, %2, %0;"                               \
                    : "+r"(tacc[mf_][h]) : "r"(t01), "r"(msk));                  \
            }                                                                    \
        }                                                                        \
    } while (0)

// MMA chain for one mf-group: re-reads this warp's B slice per ks
#define MMA_MF(cc, mf_)                                                          \
    do {                                                                         \
        _Pragma("unroll")                                                        \
        for (int nf = 0; nf < 4; ++nf)                                           \
            _Pragma("unroll")                                                    \
            for (int k = 0; k < 4; ++k) (cc)[nf][k] = 0.f;                       \
        _Pragma("unroll")                                                        \
        for (int ks = 0; ks < 4; ++ks) {                                         \
            const uint4 v0 = *(const uint4*)(sbB + (((ks * 2 + 0) * 32 + lane) << 4)); \
            const uint4 v1 = *(const uint4*)(sbB + (((ks * 2 + 1) * 32 + lane) << 4)); \
            uint32_t br0[2] = {v0.x, v0.y};                                      \
            uint32_t br1[2] = {v0.z, v0.w};                                      \
            uint32_t br2[2] = {v1.x, v1.y};                                      \
            uint32_t br3[2] = {v1.z, v1.w};                                      \
            const uint4 av = *(const uint4*)                                     \
                (smem + OFF_A + (((ks * 8 + warp_m * 4 + (mf_)) * 32 + lane) << 4)); \
            uint32_t ar[4] = {av.x, av.y, av.z, av.w};                           \
            qmma((cc)[0], ar, br0);                                              \
            qmma((cc)[1], ar, br1);                                              \
            qmma((cc)[2], ar, br2);                                              \
            qmma((cc)[3], ar, br3);                                              \
        }                                                                        \
    } while (0)

// -------- main: warp-decoupled pipeline, mf-outer ping-pong (MMA/epilogue overlap) --------
extern __shared__ char smem_dyn[];

__global__ void __launch_bounds__(256, 2) k_main() {
    char* smem = smem_dyn;
    const uint32_t sbase = smem_u32(smem);
    const int tid  = threadIdx.x;
    const int wid  = tid >> 5;
    const int lane = tid & 31;
    const int pt = blockIdx.x, sp = blockIdx.y, b = blockIdx.z;
    const int warp_m = wid >> 2;   // 0..1 -> 64 rows
    const int warp_n = wid & 3;    // 0..3 -> 32 cols

    const uint32_t* afr  = g_afr + (size_t)(b * PTILES + pt) * 4096;
    const int tile0 = sp * TPC;
    const uint32_t* bfr0 = g_bfr + (size_t)(b * NTILES + tile0) * 4096 + warp_n * 1024;
    const uint16_t* nl0 = g_nlh + b * NN + tile0 * 128 + warp_n * 32;

    const uint32_t myB[2]  = { sbase + OFF_B + (uint32_t)(wid * 2 + 0) * 4096,
                               sbase + OFF_B + (uint32_t)(wid * 2 + 1) * 4096 };
    const uint32_t myNL[2] = { sbase + OFF_NL + (uint32_t)(wid * 2 + 0) * 64,
                               sbase + OFF_NL + (uint32_t)(wid * 2 + 1) * 64 };

    // prologue: A tile (whole CTA) + this warp's B slice of tile 0 + labels
#pragma unroll
    for (int i = 0; i < 4; ++i)
        cp16(sbase + OFF_A + ((tid + (i << 8)) << 4), afr + ((tid + (i << 8)) << 2));
#pragma unroll
    for (int i = 0; i < 8; ++i)
        cp16(myB[0] + ((lane + (i << 5)) << 4), bfr0 + ((lane + (i << 5)) << 2));
    if (lane < 4) cp16(myNL[0] + (lane << 4), nl0 + (lane << 3));
    asm volatile("cp.async.commit_group;");
    asm volatile("cp.async.wait_group 0;");
    __syncthreads();    // A visible to all warps; warps decoupled after this

    // row labels as replicated f16x2
    uint32_t rl2[4][2];
#pragma unroll
    for (int mf = 0; mf < 4; ++mf)
#pragma unroll
        for (int h = 0; h < 2; ++h) {
            int p = pt * 128 + warp_m * 64 + mf * 16 + (lane >> 2) + h * 8;
            float frl = (p < P) ? (float)g_labels1[b * P + p] : -1.0f;
            asm("cvt.rn.f16x2.f32 %0, %1, %1;" : "=r"(rl2[mf][h]) : "f"(frl));
        }

    float racc[4][2];
    uint32_t tacc[4][2];
#pragma unroll
    for (int mf = 0; mf < 4; ++mf)
#pragma unroll
        for (int h = 0; h < 2; ++h) { racc[mf][h] = 0.f; tacc[mf][h] = 0u; }

    for (int t = 0; t < TPC; ++t) {
        const int buf = t & 1;
        // per-warp prefetch of tile t+1 into this warp's other buffer
        if (t + 1 < TPC) {
            const int nb = buf ^ 1;
            const uint32_t* bs = bfr0 + (size_t)(t + 1) * 4096;
#pragma unroll
            for (int i = 0; i < 8; ++i)
                cp16(myB[nb] + ((lane + (i << 5)) << 4), bs + ((lane + (i << 5)) << 2));
            if (lane < 4) cp16(myNL[nb] + (lane << 4), nl0 + (t + 1) * 128 + (lane << 3));
        }
        asm volatile("cp.async.commit_group;");
        asm volatile("cp.async.wait_group 1;");   // this warp's tile-t slice complete
        __syncwarp();

        const char* sbB = smem + OFF_B + (wid * 2 + buf) * 4096;
        const uint32_t* nlS = (const uint32_t*)(smem + OFF_NL + (wid * 2 + buf) * 64)
                              + (lane & 3);
        uint32_t cl2[4] = { nlS[0], nlS[4], nlS[8], nlS[12] };

        // mf-outer ping-pong: MMA chain of mf overlaps epilogue of mf-1
        float cA[4][4], cB[4][4];
        MMA_MF(cA, 0);
        MMA_MF(cB, 1);
        EPILOGUE_MF(cA, 0);      // runs while mf=1 MMAs drain the tensor pipe
        MMA_MF(cA, 2);
        EPILOGUE_MF(cB, 1);
        MMA_MF(cB, 3);
        EPILOGUE_MF(cA, 2);
        EPILOGUE_MF(cB, 3);

        // drain packed tile-accumulators to f32 (keeps f16 sums tiny)
#pragma unroll
        for (int mf = 0; mf < 4; ++mf)
#pragma unroll
            for (int h = 0; h < 2; ++h) {
                float lo, hi;
                asm("{ .reg .b16 l, u;\n\t"
                    "  mov.b32 {l, u}, %2;\n\t"
                    "  cvt.f32.f16 %0, l;\n\t"
                    "  cvt.f32.f16 %1, u; }"
                    : "=f"(lo), "=f"(hi) : "r"(tacc[mf][h]));
                racc[mf][h] += lo + hi;
                tacc[mf][h] = 0u;
            }
        // no CTA barrier: buffers are warp-private
    }

    // reduce across the 4 lanes of each quad (they share rows), then atomadd
#pragma unroll
    for (int mf = 0; mf < 4; ++mf)
#pragma unroll
        for (int h = 0; h < 2; ++h) {
            float v = racc[mf][h];
            v += __shfl_xor_sync(0xffffffffu, v, 1);
            v += __shfl_xor_sync(0xffffffffu, v, 2);
            if ((lane & 3) == 0) {
                int p = pt * 128 + warp_m * 64 + mf * 16 + (lane >> 2) + h * 8;
                if (p < P) atomicAdd(&g_negsum[b * P + p], v);
            }
        }
}

// -------- finalize --------
__global__ void k_final(float* __restrict__ out) {
    const int tid = threadIdx.x;
    float sl[2] = {0.f, 0.f}, sm[2] = {0.f, 0.f};
    for (int p = tid; p < P; p += blockDim.x) {
#pragma unroll
        for (int b = 0; b < 2; ++b) {
            int i = b * P + p;
            float pe    = expf(g_pos1[i]);
            float ns    = g_negsum[i];
            float lossn = -logf(pe / (pe + ns + EPS) + EPS);
            float m     = g_mask1[i];
            sl[b] += m * lossn;
            sm[b] += m;
        }
    }
    __shared__ float red[4][256];
    red[0][tid] = sl[0]; red[1][tid] = sl[1];
    red[2][tid] = sm[0]; red[3][tid] = sm[1];
    __syncthreads();
    for (int s = 128; s > 0; s >>= 1) {
        if (tid < s) {
#pragma unroll
            for (int k = 0; k < 4; ++k) red[k][tid] += red[k][tid + s];
        }
        __syncthreads();
    }
    if (tid == 0) {
        float l0 = red[0][0] / (red[2][0] + EPS);
        float l1 = red[1][0] / (red[3][0] + EPS);
        out[0] = 0.1f * (l0 + l1);
    }
}

// -------- launch --------
extern "C" void kernel_launch(void* const* d_in, const int* in_sizes, int n_in,
                              void* d_out, int out_size) {
    const float* feats_view1 = (const float*)d_in[0];  // [B,D,240,240]
    const float* pos_feats1  = (const float*)d_in[1];  // [B,D,60,60]
    const float* pos_feats2  = (const float*)d_in[2];  // [B,D,60,60]
    const float* pl1         = (const float*)d_in[3];
    const float* pl2         = (const float*)d_in[4];
    const float* npl         = (const float*)d_in[5];  // [B,C,240,240]

    cudaFuncSetAttribute(k_main, cudaFuncAttributeMaxDynamicSharedMemorySize, SMEM_BYTES);

    k_zero<<<(B * P + 255) / 256, 256>>>();
    k_neglabels<<<(B * NN + 255) / 256, 256>>>(npl);
    k_anchor<<<(B * P + 127) / 128, 128>>>(pos_feats1, pos_feats2, pl1, pl2);
    k_convert_neg<<<dim3(NTILES, B), 256>>>(feats_view1);
    k_convert_a<<<dim3(PTILES, B), 256>>>(pos_feats1);

    k_main<<<dim3(PTILES, SPLIT, B), 256, SMEM_BYTES>>>();

    k_final<<<1, 256>>>((float*)d_out);
}

// round 17
// speedup vs baseline: 1.8195x; 1.1496x over previous
#include <cuda_runtime.h>
#include <cuda_bf16.h>
#include <cuda_fp16.h>
#include <cuda_fp8.h>
#include <math.h>
#include <stdint.h>

#define B 2
#define D 128
#define P 3600
#define NN 57600
#define C 19
#define GAMMA 0.75f
#define EPS 1e-8f

#define PTILES 29        // ceil(3600/128)
#define NTILES 450       // 57600/128
#define SPLIT 5
#define TPC 90           // n-tiles per CTA

// dynamic smem: A(16K) + 8 warps x 2 bufs x 4KB B slices + labels
#define OFF_A    0        // 16384
#define OFF_B    16384    // + (wid*2+buf)*4096, 65536 total
#define OFF_NL   81920    // + (wid*2+buf)*64, 1024 total
#define SMEM_BYTES 82944

#define LOG2E10 14.4269504089f   // 10 * log2(e)

// -------- device global scratch (no allocation allowed) --------
// A fragments (e4m3, pre-scaled by 10*log2e): [b][pt][ks 4][mf 8][lane 32][4 u32]
static __device__ __align__(16) uint32_t g_afr[B * PTILES * 4096];
// B fragments (e4m3): [b][nt][wn 4][ks 4][nqL 2][lane 32][4 u32]
static __device__ __align__(16) uint32_t g_bfr[B * NTILES * 4096];
static __device__ __align__(16) uint16_t g_nlh[B * NN];   // neg labels as f16 bits
static __device__ int   g_labels1[B * P];
static __device__ float g_mask1[B * P];
static __device__ float g_pos1[B * P];
static __device__ float g_negsum[B * P];

// -------- PTX helpers --------
__device__ __forceinline__ uint32_t smem_u32(const void* p) {
    uint32_t a;
    asm("{ .reg .u64 t; cvta.to.shared.u64 t, %1; cvt.u32.u64 %0, t; }" : "=r"(a) : "l"(p));
    return a;
}
__device__ __forceinline__ void cp16(uint32_t dst, const void* src) {
    asm volatile("cp.async.cg.shared.global [%0], [%1], 16;" :: "r"(dst), "l"(src));
}

// -------- fused precompute: neg labels (f16) + anchor + zero --------
__global__ void k_pre(const float* __restrict__ npl,
                      const float* __restrict__ f1, const float* __restrict__ f2,
                      const float* __restrict__ pl1, const float* __restrict__ pl2) {
    int i = blockIdx.x * blockDim.x + threadIdx.x;

    if (i < B * NN) {
        int b = i / NN, n = i % NN;
        const float* base = npl + (size_t)b * C * NN + n;
        float best = base[0];
        int bi = 0;
#pragma unroll
        for (int c = 1; c < C; ++c) {
            float v = base[(size_t)c * NN];
            if (v > best) { best = v; bi = c; }
        }
        __half h = __int2half_rn(bi);
        g_nlh[i] = __half_as_ushort(h);
    }

    if (i < B * P) {
        int b = i / P, p = i % P;
        g_negsum[i] = 0.0f;

        const float* a  = f1 + (size_t)b * D * P + p;
        const float* bb = f2 + (size_t)b * D * P + p;
        float s = 0.0f;
#pragma unroll 16
        for (int d = 0; d < D; ++d) s += a[(size_t)d * P] * bb[(size_t)d * P];
        g_pos1[i] = s * 10.0f;

        const float* q1 = pl1 + (size_t)b * C * P + p;
        const float* q2 = pl2 + (size_t)b * C * P + p;
        float best = q1[0];
        int bi = 0, m = 0;
        bool found = ((q1[0] < q2[0]) && (q2[0] > GAMMA));
#pragma unroll
        for (int c = 1; c < C; ++c) {
            float v1 = q1[(size_t)c * P], v2 = q2[(size_t)c * P];
            if (v1 > best) { best = v1; bi = c; }
            if (!found && (v1 < v2) && (v2 > GAMMA)) { found = true; m = c; }
        }
        g_labels1[i] = bi;
        g_mask1[i]   = (float)m;
    }
}

// -------- pack helper: 4 floats -> 4 e4m3 bytes in a u32 --------
__device__ __forceinline__ uint32_t pack_fp8x4(float v0, float v1, float v2, float v3) {
    uint32_t b0 = __nv_cvt_float_to_fp8(v0, __NV_SATFINITE, __NV_E4M3);
    uint32_t b1 = __nv_cvt_float_to_fp8(v1, __NV_SATFINITE, __NV_E4M3);
    uint32_t b2 = __nv_cvt_float_to_fp8(v2, __NV_SATFINITE, __NV_E4M3);
    uint32_t b3 = __nv_cvt_float_to_fp8(v3, __NV_SATFINITE, __NV_E4M3);
    return b0 | (b1 << 8) | (b2 << 16) | (b3 << 24);
}

// -------- convert neg feats -> e4m3 B fragments, warp_n-sliced layout --------
// src mapping bits: q[0:1] lane[2:6] nq[7:9] ks[10:11]; nf = nq*2+(q>>1), r = q&1
// dst u32 index: wn*1024 + ks*256 + nqL*128 + lane*4 + q  (wn = nq>>1, nqL = nq&1)
__global__ void k_convert_neg(const float* __restrict__ neg) {
    int nt = blockIdx.x, b = blockIdx.y;
    const float* src = neg + (size_t)b * D * NN;
    uint32_t* dst = g_bfr + (size_t)(b * NTILES + nt) * 4096;
#pragma unroll
    for (int it = 0; it < 16; ++it) {
        int o = threadIdx.x + it * 256;
        int q    = o & 3;
        int lane = (o >> 2) & 31;
        int nq   = (o >> 7) & 7;
        int ks   = o >> 10;
        int nf = nq * 2 + (q >> 1);
        int r  = q & 1;
        int n  = nt * 128 + nf * 8 + (lane >> 2);
        int kb = ks * 32 + (lane & 3) * 4 + r * 16;
        float v0 = src[(size_t)(kb + 0) * NN + n];
        float v1 = src[(size_t)(kb + 1) * NN + n];
        float v2 = src[(size_t)(kb + 2) * NN + n];
        float v3 = src[(size_t)(kb + 3) * NN + n];
        int wn = nq >> 1, nqL = nq & 1;
        dst[wn * 1024 + ks * 256 + nqL * 128 + lane * 4 + q] = pack_fp8x4(v0, v1, v2, v3);
    }
}

// -------- convert anchor feats -> e4m3 A fragments, PRE-SCALED by 10*log2e --------
// u32 layout bits: r[0:1] lane[2:6] mf[7:9] ks[10:11]
__global__ void k_convert_a(const float* __restrict__ f1) {
    int pt = blockIdx.x, b = blockIdx.y;
    const float* src = f1 + (size_t)b * D * P;
    uint32_t* dst = g_afr + (size_t)(b * PTILES + pt) * 4096;
#pragma unroll
    for (int it = 0; it < 16; ++it) {
        int o = threadIdx.x + it * 256;
        int r    = o & 3;
        int lane = (o >> 2) & 31;
        int mf   = (o >> 7) & 7;
        int ks   = o >> 10;
        int row = mf * 16 + (lane >> 2) + (r & 1) * 8;
        int kb  = ks * 32 + (lane & 3) * 4 + (r >> 1) * 16;
        int p   = pt * 128 + row;
        float v0 = 0.f, v1 = 0.f, v2 = 0.f, v3 = 0.f;
        if (p < P) {
            v0 = src[(size_t)(kb + 0) * P + p] * LOG2E10;
            v1 = src[(size_t)(kb + 1) * P + p] * LOG2E10;
            v2 = src[(size_t)(kb + 2) * P + p] * LOG2E10;
            v3 = src[(size_t)(kb + 3) * P + p] * LOG2E10;
        }
        dst[o] = pack_fp8x4(v0, v1, v2, v3);
    }
}

// -------- fp8 mma.sync with f16 accumulators (D packed f16x2, 2 regs) --------
__device__ __forceinline__ void qmma16(uint32_t* c, const uint32_t* a, const uint32_t* bb) {
    asm volatile(
        "mma.sync.aligned.m16n8k32.row.col.f16.e4m3.e4m3.f16 "
        "{%0,%1}, {%2,%3,%4,%5}, {%6,%7}, {%0,%1};"
        : "+r"(c[0]), "+r"(c[1])
        : "r"(a[0]), "r"(a[1]), "r"(a[2]), "r"(a[3]), "r"(bb[0]), "r"(bb[1]));
}

// -------- main: warp-decoupled pipeline, f16-acc FP8 MMA + 3-op f16x2 epilogue --------
extern __shared__ char smem_dyn[];

__global__ void __launch_bounds__(256, 2) k_main() {
    char* smem = smem_dyn;
    const uint32_t sbase = smem_u32(smem);
    const int tid  = threadIdx.x;
    const int wid  = tid >> 5;
    const int lane = tid & 31;
    const int pt = blockIdx.x, sp = blockIdx.y, b = blockIdx.z;
    const int warp_m = wid >> 2;   // 0..1 -> 64 rows
    const int warp_n = wid & 3;    // 0..3 -> 32 cols

    const uint32_t* afr  = g_afr + (size_t)(b * PTILES + pt) * 4096;
    const int tile0 = sp * TPC;
    const uint32_t* bfr0 = g_bfr + (size_t)(b * NTILES + tile0) * 4096 + warp_n * 1024;
    const uint16_t* nl0 = g_nlh + b * NN + tile0 * 128 + warp_n * 32;

    const uint32_t myB[2]  = { sbase + OFF_B + (uint32_t)(wid * 2 + 0) * 4096,
                               sbase + OFF_B + (uint32_t)(wid * 2 + 1) * 4096 };
    const uint32_t myNL[2] = { sbase + OFF_NL + (uint32_t)(wid * 2 + 0) * 64,
                               sbase + OFF_NL + (uint32_t)(wid * 2 + 1) * 64 };

    // prologue: A tile (whole CTA) + this warp's B slice of tile 0 + labels
#pragma unroll
    for (int i = 0; i < 4; ++i)
        cp16(sbase + OFF_A + ((tid + (i << 8)) << 4), afr + ((tid + (i << 8)) << 2));
#pragma unroll
    for (int i = 0; i < 8; ++i)
        cp16(myB[0] + ((lane + (i << 5)) << 4), bfr0 + ((lane + (i << 5)) << 2));
    if (lane < 4) cp16(myNL[0] + (lane << 4), nl0 + (lane << 3));
    asm volatile("cp.async.commit_group;");
    asm volatile("cp.async.wait_group 0;");
    __syncthreads();    // A visible to all warps; warps decoupled after this

    // row labels as replicated f16x2
    uint32_t rl2[4][2];
#pragma unroll
    for (int mf = 0; mf < 4; ++mf)
#pragma unroll
        for (int h = 0; h < 2; ++h) {
            int p = pt * 128 + warp_m * 64 + mf * 16 + (lane >> 2) + h * 8;
            float frl = (p < P) ? (float)g_labels1[b * P + p] : -1.0f;
            asm("cvt.rn.f16x2.f32 %0, %1, %1;" : "=r"(rl2[mf][h]) : "f"(frl));
        }

    float racc[4][2];
    uint32_t tacc[4][2];
#pragma unroll
    for (int mf = 0; mf < 4; ++mf)
#pragma unroll
        for (int h = 0; h < 2; ++h) { racc[mf][h] = 0.f; tacc[mf][h] = 0u; }

    for (int t = 0; t < TPC; ++t) {
        const int buf = t & 1;
        // per-warp prefetch of tile t+1 into this warp's other buffer
        if (t + 1 < TPC) {
            const int nb = buf ^ 1;
            const uint32_t* bs = bfr0 + (size_t)(t + 1) * 4096;
#pragma unroll
            for (int i = 0; i < 8; ++i)
                cp16(myB[nb] + ((lane + (i << 5)) << 4), bs + ((lane + (i << 5)) << 2));
            if (lane < 4) cp16(myNL[nb] + (lane << 4), nl0 + (t + 1) * 128 + (lane << 3));
        }
        asm volatile("cp.async.commit_group;");
        asm volatile("cp.async.wait_group 1;");   // this warp's tile-t slice complete
        __syncwarp();

        const char* sbB = smem + OFF_B + (wid * 2 + buf) * 4096;
        const uint32_t* nlS = (const uint32_t*)(smem + OFF_NL + (wid * 2 + buf) * 64)
                              + (lane & 3);
        uint32_t cl2[4] = { nlS[0], nlS[4], nlS[8], nlS[12] };

        // accumulators: packed f16x2, 2 regs per (mf,nf)
        uint32_t c[4][4][2];
#pragma unroll
        for (int mf = 0; mf < 4; ++mf)
#pragma unroll
            for (int nf = 0; nf < 4; ++nf) { c[mf][nf][0] = 0u; c[mf][nf][1] = 0u; }

#pragma unroll
        for (int ks = 0; ks < 4; ++ks) {
            uint32_t br[4][2];
#pragma unroll
            for (int nql = 0; nql < 2; ++nql) {
                const uint4 v = *(const uint4*)
                    (sbB + (((ks * 2 + nql) * 32 + lane) << 4));
                br[nql * 2 + 0][0] = v.x; br[nql * 2 + 0][1] = v.y;
                br[nql * 2 + 1][0] = v.z; br[nql * 2 + 1][1] = v.w;
            }
#pragma unroll
            for (int mf = 0; mf < 4; ++mf) {
                const uint4 av = *(const uint4*)
                    (smem + OFF_A + (((ks * 8 + warp_m * 4 + mf) * 32 + lane) << 4));
                uint32_t ar[4] = {av.x, av.y, av.z, av.w};
#pragma unroll
                for (int nf = 0; nf < 4; ++nf)
                    qmma16(c[mf][nf], ar, br[nf]);
            }
        }

        // epilogue: accumulators are already f16x2 log2-domain pairs -> 3 ops/pair
#pragma unroll
        for (int nf = 0; nf < 4; ++nf) {
#pragma unroll
            for (int mf = 0; mf < 4; ++mf) {
#pragma unroll
                for (int h = 0; h < 2; ++h) {
                    uint32_t t01 = c[mf][nf][h], msk;
                    asm("ex2.approx.f16x2 %0, %1;" : "=r"(t01) : "r"(t01));
                    asm("set.ne.f16x2.f16x2 %0, %1, %2;"
                        : "=r"(msk) : "r"(rl2[mf][h]), "r"(cl2[nf]));
                    asm("fma.rn.f16x2 %0, %1, %2, %0;"
                        : "+r"(tacc[mf][h]) : "r"(t01), "r"(msk));
                }
            }
        }
        // drain packed accumulators to f32 every 2nd tile (sums stay small in f16)
        if (t & 1) {
#pragma unroll
            for (int mf = 0; mf < 4; ++mf)
#pragma unroll
                for (int h = 0; h < 2; ++h) {
                    float lo, hi;
                    asm("{ .reg .b16 l, u;\n\t"
                        "  mov.b32 {l, u}, %2;\n\t"
                        "  cvt.f32.f16 %0, l;\n\t"
                        "  cvt.f32.f16 %1, u; }"
                        : "=f"(lo), "=f"(hi) : "r"(tacc[mf][h]));
                    racc[mf][h] += lo + hi;
                    tacc[mf][h] = 0u;
                }
        }
        // no CTA barrier: buffers are warp-private
    }

    // reduce across the 4 lanes of each quad (they share rows), then atomadd
#pragma unroll
    for (int mf = 0; mf < 4; ++mf)
#pragma unroll
        for (int h = 0; h < 2; ++h) {
            float v = racc[mf][h];
            v += __shfl_xor_sync(0xffffffffu, v, 1);
            v += __shfl_xor_sync(0xffffffffu, v, 2);
            if ((lane & 3) == 0) {
                int p = pt * 128 + warp_m * 64 + mf * 16 + (lane >> 2) + h * 8;
                if (p < P) atomicAdd(&g_negsum[b * P + p], v);
            }
        }
}

// -------- finalize --------
__global__ void k_final(float* __restrict__ out) {
    const int tid = threadIdx.x;
    float sl[2] = {0.f, 0.f}, sm[2] = {0.f, 0.f};
    for (int p = tid; p < P; p += blockDim.x) {
#pragma unroll
        for (int b = 0; b < 2; ++b) {
            int i = b * P + p;
            float pe    = expf(g_pos1[i]);
            float ns    = g_negsum[i];
            float lossn = -logf(pe / (pe + ns + EPS) + EPS);
            float m     = g_mask1[i];
            sl[b] += m * lossn;
            sm[b] += m;
        }
    }
    __shared__ float red[4][256];
    red[0][tid] = sl[0]; red[1][tid] = sl[1];
    red[2][tid] = sm[0]; red[3][tid] = sm[1];
    __syncthreads();
    for (int s = 128; s > 0; s >>= 1) {
        if (tid < s) {
#pragma unroll
            for (int k = 0; k < 4; ++k) red[k][tid] += red[k][tid + s];
        }
        __syncthreads();
    }
    if (tid == 0) {
        float l0 = red[0][0] / (red[2][0] + EPS);
        float l1 = red[1][0] / (red[3][0] + EPS);
        out[0] = 0.1f * (l0 + l1);
    }
}

// -------- launch --------
extern "C" void kernel_launch(void* const* d_in, const int* in_sizes, int n_in,
                              void* d_out, int out_size) {
    const float* feats_view1 = (const float*)d_in[0];  // [B,D,240,240]
    const float* pos_feats1  = (const float*)d_in[1];  // [B,D,60,60]
    const float* pos_feats2  = (const float*)d_in[2];  // [B,D,60,60]
    const float* pl1         = (const float*)d_in[3];
    const float* pl2         = (const float*)d_in[4];
    const float* npl         = (const float*)d_in[5];  // [B,C,240,240]

    cudaFuncSetAttribute(k_main, cudaFuncAttributeMaxDynamicSharedMemorySize, SMEM_BYTES);

    k_pre<<<(B * NN + 255) / 256, 256>>>(npl, pos_feats1, pos_feats2, pl1, pl2);
    k_convert_neg<<<dim3(NTILES, B), 256>>>(feats_view1);
    k_convert_a<<<dim3(PTILES, B), 256>>>(pos_feats1);

    k_main<<<dim3(PTILES, SPLIT, B), 256, SMEM_BYTES>>>();

    k_final<<<1, 256>>>((float*)d_out);
}